// round 14
// baseline (speedup 1.0000x reference)
#include <cuda_runtime.h>
#include <cuda_fp16.h>
#include <math.h>
#include <stdint.h>

#define NN 50000
#define EE 800000
#define DH 256
#define DC 64
#define NB 196           // (NN + 255) / 256
#define NHALF 25088      // 196 row-tiles * 128

// ---------------- device scratch ----------------
// Buffer roles: agg always writes g_h1h; GEMMs alternate g_h0h / g_h2h as output,
// so a GEMM half never overwrites the buffer the concurrent agg half is gathering from.
__device__ __half g_h0h[NN * DH];
__device__ __half g_h1h[NN * DH];
__device__ __half g_h2h[NN * DH];
__device__ __half g_xh[NN * DH];
__device__ __half g_Wt1h[DH * DH];   // W^T fp16: [n][k], K contiguous
__device__ __half g_Wt2h[DH * DH];
__device__ __half g_Wt3h[DC * DH];
__device__ float  g_dinv[NN];
__device__ int    g_deg[NN];
__device__ int    g_off[NN + 1];
__device__ int    g_cur[NN];
__device__ int    g_csr[EE];
__device__ int    g_idx[2 * EE];
__device__ int    g_part[256];
__device__ int    g_is64;

// ---------------- PTX helpers ----------------
__device__ __forceinline__ uint32_t s2u(const void* p) {
    uint32_t a;
    asm("{ .reg .u64 t; cvta.to.shared.u64 t, %1; cvt.u32.u64 %0, t; }" : "=r"(a) : "l"(p));
    return a;
}
__device__ __forceinline__ void cp16(uint32_t dst, const void* src, bool valid) {
    int sz = valid ? 16 : 0;
    asm volatile("cp.async.ca.shared.global [%0], [%1], 16, %2;"
                 :: "r"(dst), "l"(src), "r"(sz) : "memory");
}
__device__ __forceinline__ void cp_commit() {
    asm volatile("cp.async.commit_group;" ::: "memory");
}
template <int N>
__device__ __forceinline__ void cp_wait() {
    asm volatile("cp.async.wait_group %0;" :: "n"(N) : "memory");
}
__device__ __forceinline__ void mma16n8k16(float* c, const uint32_t* a, const uint32_t* b) {
    asm volatile(
        "mma.sync.aligned.m16n8k16.row.col.f32.f16.f16.f32 "
        "{%0,%1,%2,%3}, {%4,%5,%6,%7}, {%8,%9}, {%0,%1,%2,%3};"
        : "+f"(c[0]), "+f"(c[1]), "+f"(c[2]), "+f"(c[3])
        : "r"(a[0]), "r"(a[1]), "r"(a[2]), "r"(a[3]), "r"(b[0]), "r"(b[1]));
}

// ---------------- preprocessing ----------------
__global__ void zero_detect_k(const int* __restrict__ w) {
    int i = blockIdx.x * blockDim.x + threadIdx.x;
    if (i < NN) g_deg[i] = 0;
    if (blockIdx.x == 0) {
        __shared__ int any;
        if (threadIdx.x == 0) any = 0;
        __syncthreads();
        if (w[2 * threadIdx.x + 1] != 0) atomicOr(&any, 1);
        __syncthreads();
        if (threadIdx.x == 0) g_is64 = (any == 0) ? 1 : 0;
    }
}
__global__ void convert_count_k(const int* __restrict__ w) {
    int q = blockIdx.x * blockDim.x + threadIdx.x;
    if (q >= (2 * EE) / 4) return;
    int e0 = q * 4;
    int v[4];
    if (g_is64) {
        int4 a = __ldg((const int4*)&w[2 * e0]);
        int4 b = __ldg((const int4*)&w[2 * e0 + 4]);
        v[0] = a.x; v[1] = a.z; v[2] = b.x; v[3] = b.z;
    } else {
        int4 a = __ldg((const int4*)&w[e0]);
        v[0] = a.x; v[1] = a.y; v[2] = a.z; v[3] = a.w;
    }
#pragma unroll
    for (int j = 0; j < 4; j++) {
        int t = v[j];
        if (t < 0) t = 0;
        if (t >= NN) t = NN - 1;
        g_idx[e0 + j] = t;
        if (e0 + j >= EE) atomicAdd(&g_deg[t], 1);
    }
}
__global__ void block_reduce_k() {
    __shared__ int sm[256];
    int i = blockIdx.x * 256 + threadIdx.x;
    sm[threadIdx.x] = (i < NN) ? g_deg[i] : 0;
    __syncthreads();
#pragma unroll
    for (int d = 128; d > 0; d >>= 1) {
        if (threadIdx.x < d) sm[threadIdx.x] += sm[threadIdx.x + d];
        __syncthreads();
    }
    if (threadIdx.x == 0) g_part[blockIdx.x] = sm[0];
}
__global__ void scan_part_k() {
    __shared__ int sm[256];
    int t = threadIdx.x;
    int v = (t < NB) ? g_part[t] : 0;
    sm[t] = v;
    __syncthreads();
#pragma unroll
    for (int d = 1; d < 256; d <<= 1) {
        int u = (t >= d) ? sm[t - d] : 0;
        __syncthreads();
        sm[t] += u;
        __syncthreads();
    }
    g_part[t] = sm[t] - v;
}
__global__ void write_off_k() {
    __shared__ int sm[256];
    int t = threadIdx.x;
    int i = blockIdx.x * 256 + t;
    int deg = (i < NN) ? g_deg[i] : 0;
    sm[t] = deg;
    __syncthreads();
#pragma unroll
    for (int d = 1; d < 256; d <<= 1) {
        int u = (t >= d) ? sm[t - d] : 0;
        __syncthreads();
        sm[t] += u;
        __syncthreads();
    }
    int base = g_part[blockIdx.x];
    int excl = base + sm[t] - deg;
    if (i < NN) {
        g_off[i] = excl;
        g_cur[i] = excl;
        g_dinv[i] = rsqrtf((float)(deg + 1));
        if (i == NN - 1) g_off[NN] = excl + deg;
    }
}
__global__ void scatter_k() {
    int e = blockIdx.x * blockDim.x + threadIdx.x;
    if (e < EE) {
        int c = g_idx[EE + e];
        int p = atomicAdd(&g_cur[c], 1);
        if (p < EE) g_csr[p] = g_idx[e];
    }
}
__global__ void prep_fp16_k(const float* __restrict__ W1, const float* __restrict__ W2,
                            const float* __restrict__ W3, const float* __restrict__ x) {
    int i = blockIdx.x * blockDim.x + threadIdx.x;
    if (i < DH * DH) {
        int n = i / DH, k = i % DH;
        g_Wt1h[i] = __float2half(W1[k * DH + n]);
        g_Wt2h[i] = __float2half(W2[k * DH + n]);
    }
    if (i < DC * DH) {
        int n = i / DH, k = i % DH;
        g_Wt3h[i] = __float2half(W3[k * DC + n]);
    }
    if (i < NN * DH / 2) {
        float2 v = *(const float2*)&x[2 * i];
        ((__half2*)g_xh)[i] = __floats2half2_rn(v.x, v.y);
    }
}

// ---------------- fp16 mma.sync GEMM (m16n8k16), fp16 epilogue ----------------
// ASEL: 0 = g_xh, 1 = g_h1h (agg output). DSTBUF: 0 = g_h0h, 1 = g_h2h.
// DSCALE=1: epilogue multiplies by dinv[row]. ytile0: row-tile offset (half split).
template <int BN, int WN, int MCOLS, int ASEL, int DSCALE, int DSTBUF>
__global__ void __launch_bounds__(256) mma_gemm_k(int wsel, int ytile0) {
    const __half* A = (ASEL == 0) ? (const __half*)g_xh : (const __half*)g_h1h;
    __half* DST = (DSTBUF == 0) ? (__half*)g_h0h : (__half*)g_h2h;
    const __half* Bt = (wsel == 0) ? (const __half*)g_Wt1h
                     : (wsel == 1) ? (const __half*)g_Wt2h
                                   : (const __half*)g_Wt3h;

    constexpr int ST = 40;
    constexpr int NT = WN / 8;
    __shared__ __half As[2][128 * ST];
    __shared__ __half Bs[2][BN * ST];

    const int tid = threadIdx.x;
    const int wid = tid >> 5;
    const int lane = tid & 31;
    const int t4 = lane >> 2;
    const int tk = lane & 3;
    const int wm = wid & 1;
    const int wn = wid >> 1;
    const int row0 = (ytile0 + blockIdx.y) * 128;
    const int col0 = blockIdx.x * BN;

    float c[4][NT][4];
#pragma unroll
    for (int mt = 0; mt < 4; mt++)
#pragma unroll
        for (int nt = 0; nt < NT; nt++)
#pragma unroll
            for (int j = 0; j < 4; j++) c[mt][nt][j] = 0.0f;

    const uint32_t sa[2] = { s2u(As[0]), s2u(As[1]) };
    const uint32_t sb[2] = { s2u(Bs[0]), s2u(Bs[1]) };

    auto load_chunk = [&](int kc, int st) {
#pragma unroll
        for (int i = 0; i < 2; i++) {
            int l = tid + i * 256;
            int m = l >> 2, kq = l & 3;
            bool v = (row0 + m) < NN;
            cp16(sa[st] + (uint32_t)(m * ST + kq * 8) * 2,
                 &A[(size_t)(row0 + m) * DH + kc * 32 + kq * 8], v);
        }
#pragma unroll
        for (int i = 0; i < BN / 64; i++) {
            int l = tid + i * 256;
            int n = l >> 2, kq = l & 3;
            cp16(sb[st] + (uint32_t)(n * ST + kq * 8) * 2,
                 &Bt[(size_t)(col0 + n) * DH + kc * 32 + kq * 8], true);
        }
        cp_commit();
    };

    load_chunk(0, 0);

    for (int kc = 0; kc < 8; kc++) {
        const int st = kc & 1;
        if (kc + 1 < 8) { load_chunk(kc + 1, st ^ 1); cp_wait<1>(); }
        else cp_wait<0>();
        __syncthreads();

        const __half* as = As[st];
        const __half* bs = Bs[st];
#pragma unroll
        for (int ks = 0; ks < 2; ks++) {
            const int k0 = ks * 16;
            uint32_t a[4][4];
#pragma unroll
            for (int mt = 0; mt < 4; mt++) {
                int m = wm * 64 + mt * 16 + t4;
                a[mt][0] = *(const uint32_t*)&as[m * ST + k0 + 2 * tk];
                a[mt][1] = *(const uint32_t*)&as[(m + 8) * ST + k0 + 2 * tk];
                a[mt][2] = *(const uint32_t*)&as[m * ST + k0 + 2 * tk + 8];
                a[mt][3] = *(const uint32_t*)&as[(m + 8) * ST + k0 + 2 * tk + 8];
            }
            uint32_t b[NT][2];
#pragma unroll
            for (int nt = 0; nt < NT; nt++) {
                int n = wn * WN + nt * 8 + t4;
                b[nt][0] = *(const uint32_t*)&bs[n * ST + k0 + 2 * tk];
                b[nt][1] = *(const uint32_t*)&bs[n * ST + k0 + 2 * tk + 8];
            }
#pragma unroll
            for (int mt = 0; mt < 4; mt++)
#pragma unroll
                for (int nt = 0; nt < NT; nt++)
                    mma16n8k16(c[mt][nt], a[mt], b[nt]);
        }
        __syncthreads();
    }

#pragma unroll
    for (int mt = 0; mt < 4; mt++) {
        int r0g = row0 + wm * 64 + mt * 16 + t4;
        int r1g = r0g + 8;
        float s0 = 1.0f, s1 = 1.0f;
        if (DSCALE) {
            s0 = (r0g < NN) ? g_dinv[r0g] : 0.0f;
            s1 = (r1g < NN) ? g_dinv[r1g] : 0.0f;
        }
#pragma unroll
        for (int nt = 0; nt < NT; nt++) {
            int gc = col0 + wn * WN + nt * 8 + 2 * tk;
            if (r0g < NN)
                *(__half2*)&DST[(size_t)r0g * MCOLS + gc] =
                    __floats2half2_rn(c[mt][nt][0] * s0, c[mt][nt][1] * s0);
            if (r1g < NN)
                *(__half2*)&DST[(size_t)r1g * MCOLS + gc] =
                    __floats2half2_rn(c[mt][nt][2] * s1, c[mt][nt][3] * s1);
        }
    }
}

// ---------------- aggregation D=256 (warp per node, unroll 8) ----------------
// SRCBUF: 0 = gather g_h0h, 1 = gather g_h2h. Dst always g_h1h. node0: half offset.
__device__ __forceinline__ void acc_add8s(float* acc, uint4 v, float s) {
    const __half2* h = (const __half2*)&v;
#pragma unroll
    for (int i = 0; i < 4; i++) {
        float2 f = __half22float2(h[i]);
        acc[2 * i]     = fmaf(f.x, s, acc[2 * i]);
        acc[2 * i + 1] = fmaf(f.y, s, acc[2 * i + 1]);
    }
}

template <int SRCSC, int SRCBUF>
__global__ void __launch_bounds__(256) agg256_k(const float* __restrict__ bias, int node0) {
    const int node = node0 + blockIdx.x * 8 + (threadIdx.x >> 5);
    if (node >= NN) return;
    const int lane = threadIdx.x & 31;
    const uint4* base = (SRCBUF == 0) ? (const uint4*)g_h0h : (const uint4*)g_h2h;

    float acc[8];
#pragma unroll
    for (int i = 0; i < 8; i++) acc[i] = 0.0f;
    {
        uint4 v = __ldg(&base[(size_t)node * 32 + lane]);
        float ss = SRCSC ? g_dinv[node] : 1.0f;
        acc_add8s(acc, v, ss);
    }

    const int s = g_off[node], e = g_off[node + 1];
    int p = s;
    for (; p + 8 <= e; p += 8) {
        int r[8];
#pragma unroll
        for (int j = 0; j < 8; j++) r[j] = __ldg(&g_csr[p + j]);
        float sc8[8];
#pragma unroll
        for (int j = 0; j < 8; j++) sc8[j] = SRCSC ? __ldg(&g_dinv[r[j]]) : 1.0f;
        uint4 vv[8];
#pragma unroll
        for (int j = 0; j < 8; j++) vv[j] = __ldg(&base[(size_t)r[j] * 32 + lane]);
#pragma unroll
        for (int j = 0; j < 8; j++) acc_add8s(acc, vv[j], sc8[j]);
    }
    for (; p < e; p++) {
        int r = __ldg(&g_csr[p]);
        float ss = SRCSC ? __ldg(&g_dinv[r]) : 1.0f;
        acc_add8s(acc, __ldg(&base[(size_t)r * 32 + lane]), ss);
    }

    const float sc = g_dinv[node];
    const float* bb = &bias[lane * 8];
    __half2 o[4];
#pragma unroll
    for (int q = 0; q < 4; q++) {
        float ox = fmaxf(fmaf(acc[2 * q], sc, bb[2 * q]), 0.f);
        float oy = fmaxf(fmaf(acc[2 * q + 1], sc, bb[2 * q + 1]), 0.f);
        o[q] = __floats2half2_rn(ox, oy);
    }
    *(uint4*)&g_h1h[(size_t)node * 256 + lane * 8] = *(uint4*)o;
}

// ---------------- FUSED: agg D=64 + dense 64x64 + sigmoid -> d_out (reads g_h2h) ----------------
__global__ void __launch_bounds__(256) agg64_sig_k(const float* __restrict__ b3,
                                                   const float* __restrict__ W4,
                                                   const float* __restrict__ b4,
                                                   float* __restrict__ out) {
    __shared__ float w4s[DC * DC];
    __shared__ float b4s[DC];
    __shared__ float hrow[8][DC];

    const int tid = threadIdx.x;
    const int wid = tid >> 5;
    const int lane = tid & 31;

#pragma unroll
    for (int i = 0; i < DC * DC / 256; i++)
        w4s[tid + i * 256] = W4[tid + i * 256];
    if (tid < DC) b4s[tid] = b4[tid];
    __syncthreads();

    const int node = blockIdx.x * 8 + wid;
    if (node >= NN) return;

    const __half2* base = (const __half2*)g_h2h;  // gemm W3 output, row stride 32 half2

    float2 acc = __half22float2(__ldg(&base[(size_t)node * 32 + lane]));
    const int s = g_off[node], e = g_off[node + 1];
    int p = s;
    for (; p + 8 <= e; p += 8) {
        int r[8];
#pragma unroll
        for (int j = 0; j < 8; j++) r[j] = __ldg(&g_csr[p + j]);
        float2 f[8];
#pragma unroll
        for (int j = 0; j < 8; j++) f[j] = __half22float2(__ldg(&base[(size_t)r[j] * 32 + lane]));
#pragma unroll
        for (int j = 0; j < 8; j++) { acc.x += f[j].x; acc.y += f[j].y; }
    }
    for (; p < e; p++) {
        int r = __ldg(&g_csr[p]);
        float2 f = __half22float2(__ldg(&base[(size_t)r * 32 + lane]));
        acc.x += f.x; acc.y += f.y;
    }

    const float sc = g_dinv[node];
    hrow[wid][2 * lane]     = fmaf(acc.x, sc, b3[2 * lane]);
    hrow[wid][2 * lane + 1] = fmaf(acc.y, sc, b3[2 * lane + 1]);
    __syncwarp();

    const float* h = hrow[wid];
    float o0 = b4s[lane], o1 = b4s[lane + 32];
#pragma unroll
    for (int k = 0; k < DC; k++) {
        float hv = h[k];
        o0 = fmaf(hv, w4s[k * DC + lane], o0);
        o1 = fmaf(hv, w4s[k * DC + lane + 32], o1);
    }
    out[(size_t)node * DC + lane]      = 1.0f / (1.0f + expf(-o0));
    out[(size_t)node * DC + lane + 32] = 1.0f / (1.0f + expf(-o1));
}

// ---------------- launch ----------------
extern "C" void kernel_launch(void* const* d_in, const int* in_sizes, int n_in,
                              void* d_out, int out_size) {
    const float* x  = (const float*)d_in[0];
    const int* eiw  = (const int*)d_in[1];
    const float* W1 = (const float*)d_in[2];
    const float* b1 = (const float*)d_in[3];
    const float* W2 = (const float*)d_in[4];
    const float* b2 = (const float*)d_in[5];
    const float* W3 = (const float*)d_in[6];
    const float* b3 = (const float*)d_in[7];
    const float* W4 = (const float*)d_in[8];
    const float* b4 = (const float*)d_in[9];

    cudaStream_t s2;
    cudaStreamCreateWithFlags(&s2, cudaStreamNonBlocking);
    cudaEvent_t evF, evJ, eA[5], eB[5];
    cudaEventCreateWithFlags(&evF, cudaEventDisableTiming);
    cudaEventCreateWithFlags(&evJ, cudaEventDisableTiming);
    for (int i = 0; i < 5; i++) {
        cudaEventCreateWithFlags(&eA[i], cudaEventDisableTiming);
        cudaEventCreateWithFlags(&eB[i], cudaEventDisableTiming);
    }

    cudaEventRecord(evF, 0);
    cudaStreamWaitEvent(s2, evF, 0);

    // s2: edge preprocessing (feeds aggregation only)
    zero_detect_k<<<NB, 256, 0, s2>>>(eiw);
    convert_count_k<<<(2 * EE / 4 + 255) / 256, 256, 0, s2>>>(eiw);
    block_reduce_k<<<NB, 256, 0, s2>>>();
    scan_part_k<<<1, 256, 0, s2>>>();
    write_off_k<<<NB, 256, 0, s2>>>();
    scatter_k<<<(EE + 255) / 256, 256, 0, s2>>>();
    cudaEventRecord(evJ, s2);

    const int MT = 391;                    // row tiles
    const int H1 = 196, H2 = MT - H1;      // half split (196*128 = 25088 rows)
    const int AGH1 = NHALF / 8;            // 3136 blocks (nodes 0..25087)
    const int AGH2 = (NN - NHALF + 7) / 8; // 3114 blocks

    // main: fp16 prep + full layer-1 GEMM (raw output; x @ W1 -> h0h)
    prep_fp16_k<<<(NN * DH / 2 + 255) / 256, 256>>>(W1, W2, W3, x);
    mma_gemm_k<128, 32, DH, 0, 0, 0><<<dim3(2, MT), 256>>>(0, 0);

    cudaStreamWaitEvent(0, evJ, 0);

    // Pipelined boundaries. Pattern per boundary i:
    //   main: agg half1 -> record eA -> agg half2 -> gemm half2 -> wait eB
    //   s2:   wait eA -> gemm half1 -> record eB
    // agg reads SRCBUF (prev gemm out), writes h1h; gemm reads h1h own rows, writes DSTBUF.
    // SRCBUF != DSTBUF at every boundary, so the overlap is race-free.

    // B1: agg1 (src h0h, per-src dinv) ; gemm W2 -> h2h
    agg256_k<1, 0><<<AGH1, 256>>>(b1, 0);
    cudaEventRecord(eA[0], 0);
    cudaStreamWaitEvent(s2, eA[0], 0);
    mma_gemm_k<128, 32, DH, 1, 1, 1><<<dim3(2, H1), 256, 0, s2>>>(1, 0);
    cudaEventRecord(eB[0], s2);
    agg256_k<1, 0><<<AGH2, 256>>>(b1, NHALF);
    mma_gemm_k<128, 32, DH, 1, 1, 1><<<dim3(2, H2), 256>>>(1, H1);
    cudaStreamWaitEvent(0, eB[0], 0);

    // B2: agg2 (src h2h) ; gemm W2 -> h0h
    agg256_k<0, 1><<<AGH1, 256>>>(b2, 0);
    cudaEventRecord(eA[1], 0);
    cudaStreamWaitEvent(s2, eA[1], 0);
    mma_gemm_k<128, 32, DH, 1, 1, 0><<<dim3(2, H1), 256, 0, s2>>>(1, 0);
    cudaEventRecord(eB[1], s2);
    agg256_k<0, 1><<<AGH2, 256>>>(b2, NHALF);
    mma_gemm_k<128, 32, DH, 1, 1, 0><<<dim3(2, H2), 256>>>(1, H1);
    cudaStreamWaitEvent(0, eB[1], 0);

    // B3: agg3 (src h0h) ; gemm W2 -> h2h
    agg256_k<0, 0><<<AGH1, 256>>>(b2, 0);
    cudaEventRecord(eA[2], 0);
    cudaStreamWaitEvent(s2, eA[2], 0);
    mma_gemm_k<128, 32, DH, 1, 1, 1><<<dim3(2, H1), 256, 0, s2>>>(1, 0);
    cudaEventRecord(eB[2], s2);
    agg256_k<0, 0><<<AGH2, 256>>>(b2, NHALF);
    mma_gemm_k<128, 32, DH, 1, 1, 1><<<dim3(2, H2), 256>>>(1, H1);
    cudaStreamWaitEvent(0, eB[2], 0);

    // B4: agg4 (src h2h) ; gemm W2 -> h0h
    agg256_k<0, 1><<<AGH1, 256>>>(b2, 0);
    cudaEventRecord(eA[3], 0);
    cudaStreamWaitEvent(s2, eA[3], 0);
    mma_gemm_k<128, 32, DH, 1, 1, 0><<<dim3(2, H1), 256, 0, s2>>>(1, 0);
    cudaEventRecord(eB[3], s2);
    agg256_k<0, 1><<<AGH2, 256>>>(b2, NHALF);
    mma_gemm_k<128, 32, DH, 1, 1, 0><<<dim3(2, H2), 256>>>(1, H1);
    cudaStreamWaitEvent(0, eB[3], 0);

    // B5: agg5 (src h0h) ; gemm W3 (64 cols) -> h2h
    agg256_k<0, 0><<<AGH1, 256>>>(b2, 0);
    cudaEventRecord(eA[4], 0);
    cudaStreamWaitEvent(s2, eA[4], 0);
    mma_gemm_k<64, 16, DC, 1, 1, 1><<<dim3(1, H1), 256, 0, s2>>>(2, 0);
    cudaEventRecord(eB[4], s2);
    agg256_k<0, 0><<<AGH2, 256>>>(b2, NHALF);
    mma_gemm_k<64, 16, DC, 1, 1, 1><<<dim3(1, H2), 256>>>(2, H1);
    cudaStreamWaitEvent(0, eB[4], 0);

    // final: agg3 (b3) + dense W4 + sigmoid -> out (reads h2h)
    agg64_sig_k<<<(NN + 7) / 8, 256>>>(b3, W4, b4, (float*)d_out);
}

// round 15
// speedup vs baseline: 1.0501x; 1.0501x over previous
#include <cuda_runtime.h>
#include <cuda_fp16.h>
#include <math.h>
#include <stdint.h>

#define NN 50000
#define EE 800000
#define DH 256
#define DC 64
#define NB 196           // (NN + 255) / 256

// ---------------- device scratch ----------------
__device__ __half g_h0h[NN * DH];    // GEMM output (fp16) -> agg gather input
__device__ __half g_h1h[NN * DH];    // agg output (fp16) -> next GEMM A
__device__ __half g_xh[NN * DH];     // input features converted to fp16
__device__ __half g_Wt1h[DH * DH];   // W^T fp16: [n][k], K contiguous
__device__ __half g_Wt2h[DH * DH];
__device__ __half g_Wt3h[DC * DH];
__device__ float  g_dinv[NN];
__device__ int    g_deg[NN];         // zero-initialized at load; re-zeroed by scatter_k tail
__device__ int    g_off[NN + 1];
__device__ int    g_cur[NN];
__device__ int    g_csr[EE];
__device__ int    g_idx[2 * EE];
__device__ int    g_part[256];
__device__ int    g_is64;

// ---------------- PTX helpers ----------------
__device__ __forceinline__ uint32_t s2u(const void* p) {
    uint32_t a;
    asm("{ .reg .u64 t; cvta.to.shared.u64 t, %1; cvt.u32.u64 %0, t; }" : "=r"(a) : "l"(p));
    return a;
}
__device__ __forceinline__ void cp16(uint32_t dst, const void* src, bool valid) {
    int sz = valid ? 16 : 0;
    asm volatile("cp.async.ca.shared.global [%0], [%1], 16, %2;"
                 :: "r"(dst), "l"(src), "r"(sz) : "memory");
}
__device__ __forceinline__ void cp_commit() {
    asm volatile("cp.async.commit_group;" ::: "memory");
}
template <int N>
__device__ __forceinline__ void cp_wait() {
    asm volatile("cp.async.wait_group %0;" :: "n"(N) : "memory");
}
__device__ __forceinline__ void mma16n8k16(float* c, const uint32_t* a, const uint32_t* b) {
    asm volatile(
        "mma.sync.aligned.m16n8k16.row.col.f32.f16.f16.f32 "
        "{%0,%1,%2,%3}, {%4,%5,%6,%7}, {%8,%9}, {%0,%1,%2,%3};"
        : "+f"(c[0]), "+f"(c[1]), "+f"(c[2]), "+f"(c[3])
        : "r"(a[0]), "r"(a[1]), "r"(a[2]), "r"(a[3]), "r"(b[0]), "r"(b[1]));
}

// ---------------- edge dtype detection (1 block; g_deg zeroing moved to scatter_k) ----------------
__global__ void detect_k(const int* __restrict__ w) {
    __shared__ int any;
    if (threadIdx.x == 0) any = 0;
    __syncthreads();
    if (w[2 * threadIdx.x + 1] != 0) atomicOr(&any, 1);
    __syncthreads();
    if (threadIdx.x == 0) g_is64 = (any == 0) ? 1 : 0;
}
// convert + fused degree count, vectorized: each thread handles 4 entries.
__global__ void convert_count_k(const int* __restrict__ w) {
    int q = blockIdx.x * blockDim.x + threadIdx.x;     // quad index
    if (q >= (2 * EE) / 4) return;
    int e0 = q * 4;
    int v[4];
    if (g_is64) {
        int4 a = __ldg((const int4*)&w[2 * e0]);
        int4 b = __ldg((const int4*)&w[2 * e0 + 4]);
        v[0] = a.x; v[1] = a.z; v[2] = b.x; v[3] = b.z;
    } else {
        int4 a = __ldg((const int4*)&w[e0]);
        v[0] = a.x; v[1] = a.y; v[2] = a.z; v[3] = a.w;
    }
#pragma unroll
    for (int j = 0; j < 4; j++) {
        int t = v[j];
        if (t < 0) t = 0;
        if (t >= NN) t = NN - 1;
        g_idx[e0 + j] = t;
        if (e0 + j >= EE) atomicAdd(&g_deg[t], 1);
    }
}

// ---------------- parallel prefix sum ----------------
__global__ void block_reduce_k() {
    __shared__ int sm[256];
    int i = blockIdx.x * 256 + threadIdx.x;
    sm[threadIdx.x] = (i < NN) ? g_deg[i] : 0;
    __syncthreads();
#pragma unroll
    for (int d = 128; d > 0; d >>= 1) {
        if (threadIdx.x < d) sm[threadIdx.x] += sm[threadIdx.x + d];
        __syncthreads();
    }
    if (threadIdx.x == 0) g_part[blockIdx.x] = sm[0];
}
__global__ void scan_part_k() {
    __shared__ int sm[256];
    int t = threadIdx.x;
    int v = (t < NB) ? g_part[t] : 0;
    sm[t] = v;
    __syncthreads();
#pragma unroll
    for (int d = 1; d < 256; d <<= 1) {
        int u = (t >= d) ? sm[t - d] : 0;
        __syncthreads();
        sm[t] += u;
        __syncthreads();
    }
    g_part[t] = sm[t] - v;
}
__global__ void write_off_k() {
    __shared__ int sm[256];
    int t = threadIdx.x;
    int i = blockIdx.x * 256 + t;
    int deg = (i < NN) ? g_deg[i] : 0;
    sm[t] = deg;
    __syncthreads();
#pragma unroll
    for (int d = 1; d < 256; d <<= 1) {
        int u = (t >= d) ? sm[t - d] : 0;
        __syncthreads();
        sm[t] += u;
        __syncthreads();
    }
    int base = g_part[blockIdx.x];
    int excl = base + sm[t] - deg;
    if (i < NN) {
        g_off[i] = excl;
        g_cur[i] = excl;
        g_dinv[i] = rsqrtf((float)(deg + 1));
        if (i == NN - 1) g_off[NN] = excl + deg;
    }
}
// scatter + re-zero g_deg for the next graph replay (write_off no longer needs it)
__global__ void scatter_k() {
    int e = blockIdx.x * blockDim.x + threadIdx.x;
    if (e < EE) {
        int c = g_idx[EE + e];
        int p = atomicAdd(&g_cur[c], 1);
        if (p < EE) g_csr[p] = g_idx[e];
    }
    if (e < NN) g_deg[e] = 0;
}

// ---------------- fused: weight transpose+fp16 AND x -> fp16 ----------------
__global__ void prep_fp16_k(const float* __restrict__ W1, const float* __restrict__ W2,
                            const float* __restrict__ W3, const float* __restrict__ x) {
    int i = blockIdx.x * blockDim.x + threadIdx.x;
    if (i < DH * DH) {
        int n = i / DH, k = i % DH;
        g_Wt1h[i] = __float2half(W1[k * DH + n]);
        g_Wt2h[i] = __float2half(W2[k * DH + n]);
    }
    if (i < DC * DH) {
        int n = i / DH, k = i % DH;
        g_Wt3h[i] = __float2half(W3[k * DC + n]);
    }
    if (i < NN * DH / 2) {
        float2 v = *(const float2*)&x[2 * i];
        ((__half2*)g_xh)[i] = __floats2half2_rn(v.x, v.y);
    }
}

// ---------------- fp16 mma.sync GEMM (m16n8k16), fp16 epilogue ----------------
// DSCALE=1: epilogue multiplies by dinv[row]; DSCALE=0: raw (layer 1).
template <int BN, int WN, int MCOLS, int ASEL, int DSCALE>
__global__ void __launch_bounds__(256) mma_gemm_k(int wsel) {
    const __half* A = (ASEL == 0) ? (const __half*)g_xh : (const __half*)g_h1h;
    const __half* Bt = (wsel == 0) ? (const __half*)g_Wt1h
                     : (wsel == 1) ? (const __half*)g_Wt2h
                                   : (const __half*)g_Wt3h;

    constexpr int ST = 40;            // halves
    constexpr int NT = WN / 8;
    __shared__ __half As[2][128 * ST];
    __shared__ __half Bs[2][BN * ST];

    const int tid = threadIdx.x;
    const int wid = tid >> 5;
    const int lane = tid & 31;
    const int t4 = lane >> 2;
    const int tk = lane & 3;
    const int wm = wid & 1;
    const int wn = wid >> 1;
    const int row0 = blockIdx.y * 128;
    const int col0 = blockIdx.x * BN;

    float c[4][NT][4];
#pragma unroll
    for (int mt = 0; mt < 4; mt++)
#pragma unroll
        for (int nt = 0; nt < NT; nt++)
#pragma unroll
            for (int j = 0; j < 4; j++) c[mt][nt][j] = 0.0f;

    const uint32_t sa[2] = { s2u(As[0]), s2u(As[1]) };
    const uint32_t sb[2] = { s2u(Bs[0]), s2u(Bs[1]) };

    auto load_chunk = [&](int kc, int st) {
#pragma unroll
        for (int i = 0; i < 2; i++) {
            int l = tid + i * 256;
            int m = l >> 2, kq = l & 3;
            bool v = (row0 + m) < NN;
            cp16(sa[st] + (uint32_t)(m * ST + kq * 8) * 2,
                 &A[(size_t)(row0 + m) * DH + kc * 32 + kq * 8], v);
        }
#pragma unroll
        for (int i = 0; i < BN / 64; i++) {
            int l = tid + i * 256;
            int n = l >> 2, kq = l & 3;
            cp16(sb[st] + (uint32_t)(n * ST + kq * 8) * 2,
                 &Bt[(size_t)(col0 + n) * DH + kc * 32 + kq * 8], true);
        }
        cp_commit();
    };

    load_chunk(0, 0);

    for (int kc = 0; kc < 8; kc++) {
        const int st = kc & 1;
        if (kc + 1 < 8) {
            load_chunk(kc + 1, st ^ 1);
            cp_wait<1>();
        } else {
            cp_wait<0>();
        }
        __syncthreads();

        const __half* as = As[st];
        const __half* bs = Bs[st];
#pragma unroll
        for (int ks = 0; ks < 2; ks++) {
            const int k0 = ks * 16;
            uint32_t a[4][4];
#pragma unroll
            for (int mt = 0; mt < 4; mt++) {
                int m = wm * 64 + mt * 16 + t4;
                a[mt][0] = *(const uint32_t*)&as[m * ST + k0 + 2 * tk];
                a[mt][1] = *(const uint32_t*)&as[(m + 8) * ST + k0 + 2 * tk];
                a[mt][2] = *(const uint32_t*)&as[m * ST + k0 + 2 * tk + 8];
                a[mt][3] = *(const uint32_t*)&as[(m + 8) * ST + k0 + 2 * tk + 8];
            }
            uint32_t b[NT][2];
#pragma unroll
            for (int nt = 0; nt < NT; nt++) {
                int n = wn * WN + nt * 8 + t4;
                b[nt][0] = *(const uint32_t*)&bs[n * ST + k0 + 2 * tk];
                b[nt][1] = *(const uint32_t*)&bs[n * ST + k0 + 2 * tk + 8];
            }
#pragma unroll
            for (int mt = 0; mt < 4; mt++)
#pragma unroll
                for (int nt = 0; nt < NT; nt++)
                    mma16n8k16(c[mt][nt], a[mt], b[nt]);
        }
        __syncthreads();
    }

#pragma unroll
    for (int mt = 0; mt < 4; mt++) {
        int r0g = row0 + wm * 64 + mt * 16 + t4;
        int r1g = r0g + 8;
        float s0 = 1.0f, s1 = 1.0f;
        if (DSCALE) {
            s0 = (r0g < NN) ? g_dinv[r0g] : 0.0f;
            s1 = (r1g < NN) ? g_dinv[r1g] : 0.0f;
        }
#pragma unroll
        for (int nt = 0; nt < NT; nt++) {
            int gc = col0 + wn * WN + nt * 8 + 2 * tk;
            if (r0g < NN)
                *(__half2*)&g_h0h[(size_t)r0g * MCOLS + gc] =
                    __floats2half2_rn(c[mt][nt][0] * s0, c[mt][nt][1] * s0);
            if (r1g < NN)
                *(__half2*)&g_h0h[(size_t)r1g * MCOLS + gc] =
                    __floats2half2_rn(c[mt][nt][2] * s1, c[mt][nt][3] * s1);
        }
    }
}

// ---------------- aggregation D=256 (warp per node, unroll 8) ----------------
__device__ __forceinline__ void acc_add8s(float* acc, uint4 v, float s) {
    const __half2* h = (const __half2*)&v;
#pragma unroll
    for (int i = 0; i < 4; i++) {
        float2 f = __half22float2(h[i]);
        acc[2 * i]     = fmaf(f.x, s, acc[2 * i]);
        acc[2 * i + 1] = fmaf(f.y, s, acc[2 * i + 1]);
    }
}

template <int RELU, int SRCSC>
__global__ void __launch_bounds__(256) agg256_k(const float* __restrict__ bias) {
    const int node = blockIdx.x * 8 + (threadIdx.x >> 5);
    if (node >= NN) return;
    const int lane = threadIdx.x & 31;
    const uint4* base = (const uint4*)g_h0h;   // row stride 32 uint4

    float acc[8];
#pragma unroll
    for (int i = 0; i < 8; i++) acc[i] = 0.0f;
    {
        uint4 v = __ldg(&base[(size_t)node * 32 + lane]);   // self loop
        float ss = SRCSC ? g_dinv[node] : 1.0f;
        acc_add8s(acc, v, ss);
    }

    const int s = g_off[node], e = g_off[node + 1];
    int p = s;
    for (; p + 8 <= e; p += 8) {
        int r[8];
#pragma unroll
        for (int j = 0; j < 8; j++) r[j] = __ldg(&g_csr[p + j]);
        float sc8[8];
#pragma unroll
        for (int j = 0; j < 8; j++) sc8[j] = SRCSC ? __ldg(&g_dinv[r[j]]) : 1.0f;
        uint4 vv[8];
#pragma unroll
        for (int j = 0; j < 8; j++) vv[j] = __ldg(&base[(size_t)r[j] * 32 + lane]);
#pragma unroll
        for (int j = 0; j < 8; j++) acc_add8s(acc, vv[j], sc8[j]);
    }
    for (; p < e; p++) {
        int r = __ldg(&g_csr[p]);
        float ss = SRCSC ? __ldg(&g_dinv[r]) : 1.0f;
        acc_add8s(acc, __ldg(&base[(size_t)r * 32 + lane]), ss);
    }

    const float sc = g_dinv[node];
    const float* bb = &bias[lane * 8];
    __half2 o[4];
#pragma unroll
    for (int q = 0; q < 4; q++) {
        float ox = fmaf(acc[2 * q], sc, bb[2 * q]);
        float oy = fmaf(acc[2 * q + 1], sc, bb[2 * q + 1]);
        if (RELU) { ox = fmaxf(ox, 0.f); oy = fmaxf(oy, 0.f); }
        o[q] = __floats2half2_rn(ox, oy);
    }
    *(uint4*)&g_h1h[(size_t)node * 256 + lane * 8] = *(uint4*)o;
}

// ---------------- FUSED: agg D=64 + dense 64x64 + sigmoid -> d_out ----------------
__global__ void __launch_bounds__(256) agg64_sig_k(const float* __restrict__ b3,
                                                   const float* __restrict__ W4,
                                                   const float* __restrict__ b4,
                                                   float* __restrict__ out) {
    __shared__ float w4s[DC * DC];       // 16 KB, [k][j]
    __shared__ float b4s[DC];
    __shared__ float hrow[8][DC];

    const int tid = threadIdx.x;
    const int wid = tid >> 5;
    const int lane = tid & 31;

#pragma unroll
    for (int i = 0; i < DC * DC / 256; i++)
        w4s[tid + i * 256] = W4[tid + i * 256];
    if (tid < DC) b4s[tid] = b4[tid];
    __syncthreads();

    const int node = blockIdx.x * 8 + wid;
    if (node >= NN) return;

    const __half2* base = (const __half2*)g_h0h;  // row stride 32 half2

    float2 acc = __half22float2(__ldg(&base[(size_t)node * 32 + lane]));
    const int s = g_off[node], e = g_off[node + 1];
    int p = s;
    for (; p + 8 <= e; p += 8) {
        int r[8];
#pragma unroll
        for (int j = 0; j < 8; j++) r[j] = __ldg(&g_csr[p + j]);
        float2 f[8];
#pragma unroll
        for (int j = 0; j < 8; j++) f[j] = __half22float2(__ldg(&base[(size_t)r[j] * 32 + lane]));
#pragma unroll
        for (int j = 0; j < 8; j++) { acc.x += f[j].x; acc.y += f[j].y; }
    }
    for (; p < e; p++) {
        int r = __ldg(&g_csr[p]);
        float2 f = __half22float2(__ldg(&base[(size_t)r * 32 + lane]));
        acc.x += f.x; acc.y += f.y;
    }

    const float sc = g_dinv[node];
    hrow[wid][2 * lane]     = fmaf(acc.x, sc, b3[2 * lane]);
    hrow[wid][2 * lane + 1] = fmaf(acc.y, sc, b3[2 * lane + 1]);
    __syncwarp();

    const float* h = hrow[wid];
    float o0 = b4s[lane], o1 = b4s[lane + 32];
#pragma unroll
    for (int k = 0; k < DC; k++) {
        float hv = h[k];
        o0 = fmaf(hv, w4s[k * DC + lane], o0);
        o1 = fmaf(hv, w4s[k * DC + lane + 32], o1);
    }
    out[(size_t)node * DC + lane]      = 1.0f / (1.0f + expf(-o0));
    out[(size_t)node * DC + lane + 32] = 1.0f / (1.0f + expf(-o1));
}

// ---------------- launch ----------------
extern "C" void kernel_launch(void* const* d_in, const int* in_sizes, int n_in,
                              void* d_out, int out_size) {
    const float* x  = (const float*)d_in[0];
    const int* eiw  = (const int*)d_in[1];
    const float* W1 = (const float*)d_in[2];
    const float* b1 = (const float*)d_in[3];
    const float* W2 = (const float*)d_in[4];
    const float* b2 = (const float*)d_in[5];
    const float* W3 = (const float*)d_in[6];
    const float* b3 = (const float*)d_in[7];
    const float* W4 = (const float*)d_in[8];
    const float* b4 = (const float*)d_in[9];

    // Fork a second stream off the (per-thread default) capture stream.
    cudaStream_t s2;
    cudaStreamCreateWithFlags(&s2, cudaStreamNonBlocking);
    cudaEvent_t evF, evJ;
    cudaEventCreateWithFlags(&evF, cudaEventDisableTiming);
    cudaEventCreateWithFlags(&evJ, cudaEventDisableTiming);

    cudaEventRecord(evF, 0);
    cudaStreamWaitEvent(s2, evF, 0);

    // s2: edge preprocessing chain (feeds aggregation only)
    detect_k<<<1, 256, 0, s2>>>(eiw);
    convert_count_k<<<(2 * EE / 4 + 255) / 256, 256, 0, s2>>>(eiw);
    block_reduce_k<<<NB, 256, 0, s2>>>();
    scan_part_k<<<1, 256, 0, s2>>>();
    write_off_k<<<NB, 256, 0, s2>>>();
    scatter_k<<<(EE + 255) / 256, 256, 0, s2>>>();
    cudaEventRecord(evJ, s2);

    const int MT = (NN + 127) / 128;       // 391
    const dim3 gBig(DH / 128, MT);         // (2, 391)
    const dim3 gS(1, MT);                  // (1, 391)
    const int AG = (NN + 7) / 8;

    // main: fp16 prep + layer-1 GEMM (raw output, no dinv dependency)
    prep_fp16_k<<<(NN * DH / 2 + 255) / 256, 256>>>(W1, W2, W3, x);
    mma_gemm_k<128, 32, DH, 0, 0><<<gBig, 256>>>(0);

    // join: aggregation needs CSR + dinv
    cudaStreamWaitEvent(0, evJ, 0);

    // Layer 1 agg: per-src dinv scaling (GEMM output was raw), relu
    agg256_k<1, 1><<<AG, 256>>>(b1);

    // Layer 2 x4 (shared weights), relu; GEMM pre-scales by dinv
    for (int it = 0; it < 4; it++) {
        mma_gemm_k<128, 32, DH, 1, 1><<<gBig, 256>>>(1);
        agg256_k<1, 0><<<AG, 256>>>(b2);
    }

    // Layer 3: 256 -> 64 GEMM (dinv-scaled), then FUSED agg + dense 64x64 + sigmoid
    mma_gemm_k<64, 16, DC, 1, 1><<<gS, 256>>>(2);
    agg64_sig_k<<<AG, 256>>>(b3, W4, b4, (float*)d_out);
}

// round 16
// speedup vs baseline: 1.0544x; 1.0041x over previous
#include <cuda_runtime.h>
#include <cuda_fp16.h>
#include <math.h>
#include <stdint.h>

#define NN 50000
#define EE 800000
#define DH 256
#define DC 64
#define NB 196           // (NN + 255) / 256

// ---------------- device scratch ----------------
__device__ __half g_h0h[NN * DH];    // GEMM output (fp16) -> agg gather input
__device__ __half g_h1h[NN * DH];    // agg output (fp16) -> next GEMM A
__device__ __half g_xh[NN * DH];     // input features converted to fp16
__device__ __half g_Wt1h[DH * DH];   // W^T fp16: [n][k], K contiguous
__device__ __half g_Wt2h[DH * DH];
__device__ __half g_Wt3h[DC * DH];
__device__ float  g_dinv[NN];
__device__ int    g_deg[NN];         // zeroed at load; re-zeroed by scatter_k tail
__device__ int    g_off[NN + 1];
__device__ int    g_cur[NN];
__device__ int    g_csr[EE];
__device__ int    g_part[256];
__device__ int    g_is64;

// ---------------- PTX helpers ----------------
__device__ __forceinline__ uint32_t s2u(const void* p) {
    uint32_t a;
    asm("{ .reg .u64 t; cvta.to.shared.u64 t, %1; cvt.u32.u64 %0, t; }" : "=r"(a) : "l"(p));
    return a;
}
__device__ __forceinline__ void cp16(uint32_t dst, const void* src, bool valid) {
    int sz = valid ? 16 : 0;
    asm volatile("cp.async.ca.shared.global [%0], [%1], 16, %2;"
                 :: "r"(dst), "l"(src), "r"(sz) : "memory");
}
__device__ __forceinline__ void cp_commit() {
    asm volatile("cp.async.commit_group;" ::: "memory");
}
template <int N>
__device__ __forceinline__ void cp_wait() {
    asm volatile("cp.async.wait_group %0;" :: "n"(N) : "memory");
}
__device__ __forceinline__ void mma16n8k16(float* c, const uint32_t* a, const uint32_t* b) {
    asm volatile(
        "mma.sync.aligned.m16n8k16.row.col.f32.f16.f16.f32 "
        "{%0,%1,%2,%3}, {%4,%5,%6,%7}, {%8,%9}, {%0,%1,%2,%3};"
        : "+f"(c[0]), "+f"(c[1]), "+f"(c[2]), "+f"(c[3])
        : "r"(a[0]), "r"(a[1]), "r"(a[2]), "r"(a[3]), "r"(b[0]), "r"(b[1]));
}

// clamp helper
__device__ __forceinline__ int clampN(int v) {
    if (v < 0) v = 0;
    if (v >= NN) v = NN - 1;
    return v;
}

// ---------------- edge dtype detection (1 block) ----------------
__global__ void detect_k(const int* __restrict__ w) {
    __shared__ int any;
    if (threadIdx.x == 0) any = 0;
    __syncthreads();
    if (w[2 * threadIdx.x + 1] != 0) atomicOr(&any, 1);
    __syncthreads();
    if (threadIdx.x == 0) g_is64 = (any == 0) ? 1 : 0;
}

// count degrees directly from raw col words (no g_idx intermediate).
// col entry e lives at w[EE + e] (int32) or w[2*(EE + e)] (int64). 4 edges/thread.
__global__ void count_k(const int* __restrict__ w) {
    int q = blockIdx.x * blockDim.x + threadIdx.x;
    if (q >= EE / 4) return;
    int e0 = q * 4;
    int v[4];
    if (g_is64) {
        int4 a = __ldg((const int4*)&w[2 * (EE + e0)]);
        int4 b = __ldg((const int4*)&w[2 * (EE + e0) + 4]);
        v[0] = a.x; v[1] = a.z; v[2] = b.x; v[3] = b.z;
    } else {
        int4 a = __ldg((const int4*)&w[EE + e0]);
        v[0] = a.x; v[1] = a.y; v[2] = a.z; v[3] = a.w;
    }
#pragma unroll
    for (int j = 0; j < 4; j++) atomicAdd(&g_deg[clampN(v[j])], 1);
}

// ---------------- parallel prefix sum ----------------
__global__ void block_reduce_k() {
    __shared__ int sm[256];
    int i = blockIdx.x * 256 + threadIdx.x;
    sm[threadIdx.x] = (i < NN) ? g_deg[i] : 0;
    __syncthreads();
#pragma unroll
    for (int d = 128; d > 0; d >>= 1) {
        if (threadIdx.x < d) sm[threadIdx.x] += sm[threadIdx.x + d];
        __syncthreads();
    }
    if (threadIdx.x == 0) g_part[blockIdx.x] = sm[0];
}
__global__ void scan_part_k() {
    __shared__ int sm[256];
    int t = threadIdx.x;
    int v = (t < NB) ? g_part[t] : 0;
    sm[t] = v;
    __syncthreads();
#pragma unroll
    for (int d = 1; d < 256; d <<= 1) {
        int u = (t >= d) ? sm[t - d] : 0;
        __syncthreads();
        sm[t] += u;
        __syncthreads();
    }
    g_part[t] = sm[t] - v;
}
__global__ void write_off_k() {
    __shared__ int sm[256];
    int t = threadIdx.x;
    int i = blockIdx.x * 256 + t;
    int deg = (i < NN) ? g_deg[i] : 0;
    sm[t] = deg;
    __syncthreads();
#pragma unroll
    for (int d = 1; d < 256; d <<= 1) {
        int u = (t >= d) ? sm[t - d] : 0;
        __syncthreads();
        sm[t] += u;
        __syncthreads();
    }
    int base = g_part[blockIdx.x];
    int excl = base + sm[t] - deg;
    if (i < NN) {
        g_off[i] = excl;
        g_cur[i] = excl;
        g_dinv[i] = rsqrtf((float)(deg + 1));
        if (i == NN - 1) g_off[NN] = excl + deg;
    }
}

// scatter directly from raw words (row at w[e] / w[2e]); re-zero g_deg for next replay.
__global__ void scatter_k(const int* __restrict__ w) {
    int q = blockIdx.x * blockDim.x + threadIdx.x;
    if (q < EE / 4) {
        int e0 = q * 4;
        int rv[4], cv[4];
        if (g_is64) {
            int4 a = __ldg((const int4*)&w[2 * e0]);
            int4 b = __ldg((const int4*)&w[2 * e0 + 4]);
            rv[0] = a.x; rv[1] = a.z; rv[2] = b.x; rv[3] = b.z;
            int4 c = __ldg((const int4*)&w[2 * (EE + e0)]);
            int4 d = __ldg((const int4*)&w[2 * (EE + e0) + 4]);
            cv[0] = c.x; cv[1] = c.z; cv[2] = d.x; cv[3] = d.z;
        } else {
            int4 a = __ldg((const int4*)&w[e0]);
            rv[0] = a.x; rv[1] = a.y; rv[2] = a.z; rv[3] = a.w;
            int4 c = __ldg((const int4*)&w[EE + e0]);
            cv[0] = c.x; cv[1] = c.y; cv[2] = c.z; cv[3] = c.w;
        }
#pragma unroll
        for (int j = 0; j < 4; j++) {
            int cc = clampN(cv[j]);
            int p = atomicAdd(&g_cur[cc], 1);
            if (p < EE) g_csr[p] = clampN(rv[j]);
        }
    }
    int i = blockIdx.x * blockDim.x + threadIdx.x;
    if (i < NN) g_deg[i] = 0;
}

// ---------------- fused: weight transpose+fp16 AND x -> fp16 ----------------
__global__ void prep_fp16_k(const float* __restrict__ W1, const float* __restrict__ W2,
                            const float* __restrict__ W3, const float* __restrict__ x) {
    int i = blockIdx.x * blockDim.x + threadIdx.x;
    if (i < DH * DH) {
        int n = i / DH, k = i % DH;
        g_Wt1h[i] = __float2half(W1[k * DH + n]);
        g_Wt2h[i] = __float2half(W2[k * DH + n]);
    }
    if (i < DC * DH) {
        int n = i / DH, k = i % DH;
        g_Wt3h[i] = __float2half(W3[k * DC + n]);
    }
    if (i < NN * DH / 2) {
        float2 v = *(const float2*)&x[2 * i];
        ((__half2*)g_xh)[i] = __floats2half2_rn(v.x, v.y);
    }
}

// ---------------- fp16 mma.sync GEMM (m16n8k16), fp16 epilogue ----------------
template <int BN, int WN, int MCOLS, int ASEL, int DSCALE>
__global__ void __launch_bounds__(256) mma_gemm_k(int wsel) {
    const __half* A = (ASEL == 0) ? (const __half*)g_xh : (const __half*)g_h1h;
    const __half* Bt = (wsel == 0) ? (const __half*)g_Wt1h
                     : (wsel == 1) ? (const __half*)g_Wt2h
                                   : (const __half*)g_Wt3h;

    constexpr int ST = 40;            // halves
    constexpr int NT = WN / 8;
    __shared__ __half As[2][128 * ST];
    __shared__ __half Bs[2][BN * ST];

    const int tid = threadIdx.x;
    const int wid = tid >> 5;
    const int lane = tid & 31;
    const int t4 = lane >> 2;
    const int tk = lane & 3;
    const int wm = wid & 1;
    const int wn = wid >> 1;
    const int row0 = blockIdx.y * 128;
    const int col0 = blockIdx.x * BN;

    float c[4][NT][4];
#pragma unroll
    for (int mt = 0; mt < 4; mt++)
#pragma unroll
        for (int nt = 0; nt < NT; nt++)
#pragma unroll
            for (int j = 0; j < 4; j++) c[mt][nt][j] = 0.0f;

    const uint32_t sa[2] = { s2u(As[0]), s2u(As[1]) };
    const uint32_t sb[2] = { s2u(Bs[0]), s2u(Bs[1]) };

    auto load_chunk = [&](int kc, int st) {
#pragma unroll
        for (int i = 0; i < 2; i++) {
            int l = tid + i * 256;
            int m = l >> 2, kq = l & 3;
            bool v = (row0 + m) < NN;
            cp16(sa[st] + (uint32_t)(m * ST + kq * 8) * 2,
                 &A[(size_t)(row0 + m) * DH + kc * 32 + kq * 8], v);
        }
#pragma unroll
        for (int i = 0; i < BN / 64; i++) {
            int l = tid + i * 256;
            int n = l >> 2, kq = l & 3;
            cp16(sb[st] + (uint32_t)(n * ST + kq * 8) * 2,
                 &Bt[(size_t)(col0 + n) * DH + kc * 32 + kq * 8], true);
        }
        cp_commit();
    };

    load_chunk(0, 0);

    for (int kc = 0; kc < 8; kc++) {
        const int st = kc & 1;
        if (kc + 1 < 8) {
            load_chunk(kc + 1, st ^ 1);
            cp_wait<1>();
        } else {
            cp_wait<0>();
        }
        __syncthreads();

        const __half* as = As[st];
        const __half* bs = Bs[st];
#pragma unroll
        for (int ks = 0; ks < 2; ks++) {
            const int k0 = ks * 16;
            uint32_t a[4][4];
#pragma unroll
            for (int mt = 0; mt < 4; mt++) {
                int m = wm * 64 + mt * 16 + t4;
                a[mt][0] = *(const uint32_t*)&as[m * ST + k0 + 2 * tk];
                a[mt][1] = *(const uint32_t*)&as[(m + 8) * ST + k0 + 2 * tk];
                a[mt][2] = *(const uint32_t*)&as[m * ST + k0 + 2 * tk + 8];
                a[mt][3] = *(const uint32_t*)&as[(m + 8) * ST + k0 + 2 * tk + 8];
            }
            uint32_t b[NT][2];
#pragma unroll
            for (int nt = 0; nt < NT; nt++) {
                int n = wn * WN + nt * 8 + t4;
                b[nt][0] = *(const uint32_t*)&bs[n * ST + k0 + 2 * tk];
                b[nt][1] = *(const uint32_t*)&bs[n * ST + k0 + 2 * tk + 8];
            }
#pragma unroll
            for (int mt = 0; mt < 4; mt++)
#pragma unroll
                for (int nt = 0; nt < NT; nt++)
                    mma16n8k16(c[mt][nt], a[mt], b[nt]);
        }
        __syncthreads();
    }

#pragma unroll
    for (int mt = 0; mt < 4; mt++) {
        int r0g = row0 + wm * 64 + mt * 16 + t4;
        int r1g = r0g + 8;
        float s0 = 1.0f, s1 = 1.0f;
        if (DSCALE) {
            s0 = (r0g < NN) ? g_dinv[r0g] : 0.0f;
            s1 = (r1g < NN) ? g_dinv[r1g] : 0.0f;
        }
#pragma unroll
        for (int nt = 0; nt < NT; nt++) {
            int gc = col0 + wn * WN + nt * 8 + 2 * tk;
            if (r0g < NN)
                *(__half2*)&g_h0h[(size_t)r0g * MCOLS + gc] =
                    __floats2half2_rn(c[mt][nt][0] * s0, c[mt][nt][1] * s0);
            if (r1g < NN)
                *(__half2*)&g_h0h[(size_t)r1g * MCOLS + gc] =
                    __floats2half2_rn(c[mt][nt][2] * s1, c[mt][nt][3] * s1);
        }
    }
}

// ---------------- aggregation D=256 (warp per node, unroll 8) ----------------
__device__ __forceinline__ void acc_add8s(float* acc, uint4 v, float s) {
    const __half2* h = (const __half2*)&v;
#pragma unroll
    for (int i = 0; i < 4; i++) {
        float2 f = __half22float2(h[i]);
        acc[2 * i]     = fmaf(f.x, s, acc[2 * i]);
        acc[2 * i + 1] = fmaf(f.y, s, acc[2 * i + 1]);
    }
}

template <int RELU, int SRCSC>
__global__ void __launch_bounds__(256) agg256_k(const float* __restrict__ bias) {
    const int node = blockIdx.x * 8 + (threadIdx.x >> 5);
    if (node >= NN) return;
    const int lane = threadIdx.x & 31;
    const uint4* base = (const uint4*)g_h0h;   // row stride 32 uint4

    float acc[8];
#pragma unroll
    for (int i = 0; i < 8; i++) acc[i] = 0.0f;
    {
        uint4 v = __ldg(&base[(size_t)node * 32 + lane]);   // self loop
        float ss = SRCSC ? g_dinv[node] : 1.0f;
        acc_add8s(acc, v, ss);
    }

    const int s = g_off[node], e = g_off[node + 1];
    int p = s;
    for (; p + 8 <= e; p += 8) {
        int r[8];
#pragma unroll
        for (int j = 0; j < 8; j++) r[j] = __ldg(&g_csr[p + j]);
        float sc8[8];
#pragma unroll
        for (int j = 0; j < 8; j++) sc8[j] = SRCSC ? __ldg(&g_dinv[r[j]]) : 1.0f;
        uint4 vv[8];
#pragma unroll
        for (int j = 0; j < 8; j++) vv[j] = __ldg(&base[(size_t)r[j] * 32 + lane]);
#pragma unroll
        for (int j = 0; j < 8; j++) acc_add8s(acc, vv[j], sc8[j]);
    }
    for (; p < e; p++) {
        int r = __ldg(&g_csr[p]);
        float ss = SRCSC ? __ldg(&g_dinv[r]) : 1.0f;
        acc_add8s(acc, __ldg(&base[(size_t)r * 32 + lane]), ss);
    }

    const float sc = g_dinv[node];
    const float* bb = &bias[lane * 8];
    __half2 o[4];
#pragma unroll
    for (int q = 0; q < 4; q++) {
        float ox = fmaf(acc[2 * q], sc, bb[2 * q]);
        float oy = fmaf(acc[2 * q + 1], sc, bb[2 * q + 1]);
        if (RELU) { ox = fmaxf(ox, 0.f); oy = fmaxf(oy, 0.f); }
        o[q] = __floats2half2_rn(ox, oy);
    }
    *(uint4*)&g_h1h[(size_t)node * 256 + lane * 8] = *(uint4*)o;
}

// ---------------- FUSED: agg D=64 + dense 64x64 + sigmoid -> d_out ----------------
__global__ void __launch_bounds__(256) agg64_sig_k(const float* __restrict__ b3,
                                                   const float* __restrict__ W4,
                                                   const float* __restrict__ b4,
                                                   float* __restrict__ out) {
    __shared__ float w4s[DC * DC];       // 16 KB, [k][j]
    __shared__ float b4s[DC];
    __shared__ float hrow[8][DC];

    const int tid = threadIdx.x;
    const int wid = tid >> 5;
    const int lane = tid & 31;

#pragma unroll
    for (int i = 0; i < DC * DC / 256; i++)
        w4s[tid + i * 256] = W4[tid + i * 256];
    if (tid < DC) b4s[tid] = b4[tid];
    __syncthreads();

    const int node = blockIdx.x * 8 + wid;
    if (node >= NN) return;

    const __half2* base = (const __half2*)g_h0h;  // row stride 32 half2

    float2 acc = __half22float2(__ldg(&base[(size_t)node * 32 + lane]));
    const int s = g_off[node], e = g_off[node + 1];
    int p = s;
    for (; p + 8 <= e; p += 8) {
        int r[8];
#pragma unroll
        for (int j = 0; j < 8; j++) r[j] = __ldg(&g_csr[p + j]);
        float2 f[8];
#pragma unroll
        for (int j = 0; j < 8; j++) f[j] = __half22float2(__ldg(&base[(size_t)r[j] * 32 + lane]));
#pragma unroll
        for (int j = 0; j < 8; j++) { acc.x += f[j].x; acc.y += f[j].y; }
    }
    for (; p < e; p++) {
        int r = __ldg(&g_csr[p]);
        float2 f = __half22float2(__ldg(&base[(size_t)r * 32 + lane]));
        acc.x += f.x; acc.y += f.y;
    }

    const float sc = g_dinv[node];
    hrow[wid][2 * lane]     = fmaf(acc.x, sc, b3[2 * lane]);
    hrow[wid][2 * lane + 1] = fmaf(acc.y, sc, b3[2 * lane + 1]);
    __syncwarp();

    const float* h = hrow[wid];
    float o0 = b4s[lane], o1 = b4s[lane + 32];
#pragma unroll
    for (int k = 0; k < DC; k++) {
        float hv = h[k];
        o0 = fmaf(hv, w4s[k * DC + lane], o0);
        o1 = fmaf(hv, w4s[k * DC + lane + 32], o1);
    }
    out[(size_t)node * DC + lane]      = 1.0f / (1.0f + expf(-o0));
    out[(size_t)node * DC + lane + 32] = 1.0f / (1.0f + expf(-o1));
}

// ---------------- launch ----------------
extern "C" void kernel_launch(void* const* d_in, const int* in_sizes, int n_in,
                              void* d_out, int out_size) {
    const float* x  = (const float*)d_in[0];
    const int* eiw  = (const int*)d_in[1];
    const float* W1 = (const float*)d_in[2];
    const float* b1 = (const float*)d_in[3];
    const float* W2 = (const float*)d_in[4];
    const float* b2 = (const float*)d_in[5];
    const float* W3 = (const float*)d_in[6];
    const float* b3 = (const float*)d_in[7];
    const float* W4 = (const float*)d_in[8];
    const float* b4 = (const float*)d_in[9];

    // Fork a second stream off the (per-thread default) capture stream.
    cudaStream_t s2;
    cudaStreamCreateWithFlags(&s2, cudaStreamNonBlocking);
    cudaEvent_t evF, evJ;
    cudaEventCreateWithFlags(&evF, cudaEventDisableTiming);
    cudaEventCreateWithFlags(&evJ, cudaEventDisableTiming);

    cudaEventRecord(evF, 0);
    cudaStreamWaitEvent(s2, evF, 0);

    // s2: edge preprocessing chain (reads raw edge words directly; no g_idx)
    detect_k<<<1, 256, 0, s2>>>(eiw);
    count_k<<<(EE / 4 + 255) / 256, 256, 0, s2>>>(eiw);
    block_reduce_k<<<NB, 256, 0, s2>>>();
    scan_part_k<<<1, 256, 0, s2>>>();
    write_off_k<<<NB, 256, 0, s2>>>();
    scatter_k<<<(EE / 4 + 255) / 256, 256, 0, s2>>>(eiw);
    cudaEventRecord(evJ, s2);

    const int MT = (NN + 127) / 128;       // 391
    const dim3 gBig(DH / 128, MT);         // (2, 391)
    const dim3 gS(1, MT);                  // (1, 391)
    const int AG = (NN + 7) / 8;

    // main: fp16 prep + layer-1 GEMM (raw output, no dinv dependency)
    prep_fp16_k<<<(NN * DH / 2 + 255) / 256, 256>>>(W1, W2, W3, x);
    mma_gemm_k<128, 32, DH, 0, 0><<<gBig, 256>>>(0);

    // join: aggregation needs CSR + dinv
    cudaStreamWaitEvent(0, evJ, 0);

    // Layer 1 agg: per-src dinv scaling (GEMM output was raw), relu
    agg256_k<1, 1><<<AG, 256>>>(b1);

    // Layer 2 x4 (shared weights), relu; GEMM pre-scales by dinv
    for (int it = 0; it < 4; it++) {
        mma_gemm_k<128, 32, DH, 1, 1><<<gBig, 256>>>(1);
        agg256_k<1, 0><<<AG, 256>>>(b2);
    }

    // Layer 3: 256 -> 64 GEMM (dinv-scaled), then FUSED agg + dense 64x64 + sigmoid
    mma_gemm_k<64, 16, DC, 1, 1><<<gS, 256>>>(2);
    agg64_sig_k<<<AG, 256>>>(b3, W4, b4, (float*)d_out);
}